// round 7
// baseline (speedup 1.0000x reference)
#include <cuda_runtime.h>
#include <math.h>
#include <stdint.h>

#define B   2
#define N0  1536
#define N1  512
#define NTOT 2048
#define D0  1024
#define D1  512
#define H   16
#define DH  64
#define DI  1024

// ---------------- scratch ----------------
__device__ float g_qkv0[(size_t)B * N0 * 3 * DI];
__device__ float g_qkv1[(size_t)B * N1 * 3 * DI];
__device__ float g_q[(size_t)B * H * NTOT * DH];
__device__ float g_k[(size_t)B * H * NTOT * DH];
__device__ float g_v[(size_t)B * H * NTOT * DH];
__device__ float g_vt[(size_t)B * H * DH * NTOT];   // V^T per (b,h): [d][n]
__device__ float g_o[(size_t)B * NTOT * DI];
__device__ float g_wt0[(size_t)3 * DI * D0];
__device__ float g_wt1[(size_t)3 * DI * D1];
__device__ float g_wtO0[(size_t)D0 * DI];
__device__ float g_wtO1[(size_t)D1 * DI];
__device__ float g_x0r[(size_t)B * N0 * D0];
__device__ float g_x1r[(size_t)B * N1 * D1];

// ---------------- helpers ----------------
__device__ __forceinline__ uint32_t smem_u32(const void* p) {
    uint32_t a;
    asm("{ .reg .u64 t; cvta.to.shared.u64 t, %1; cvt.u32.u64 %0, t; }" : "=r"(a) : "l"(p));
    return a;
}
__device__ __forceinline__ uint32_t cvt_tf32(float x) {
    uint32_t r; asm("cvt.rna.tf32.f32 %0, %1;" : "=r"(r) : "f"(x)); return r;
}
__device__ __forceinline__ float tf(float x) { return __uint_as_float(cvt_tf32(x)); }
__device__ __forceinline__ float ex2f(float x) {
    float r; asm("ex2.approx.ftz.f32 %0, %1;" : "=f"(r) : "f"(x)); return r;
}
__device__ __forceinline__ void mma8(float (&d)[4], const uint32_t* a, const uint32_t* b) {
    asm volatile("mma.sync.aligned.m16n8k8.row.col.f32.tf32.tf32.f32 "
        "{%0,%1,%2,%3}, {%4,%5,%6,%7}, {%8,%9}, {%0,%1,%2,%3};"
        : "+f"(d[0]), "+f"(d[1]), "+f"(d[2]), "+f"(d[3])
        : "r"(a[0]), "r"(a[1]), "r"(a[2]), "r"(a[3]), "r"(b[0]), "r"(b[1]));
}
__device__ __forceinline__ void cpa16(uint32_t dst, const void* src) {
    asm volatile("cp.async.cg.shared.global [%0], [%1], 16;" :: "r"(dst), "l"(src));
}
#define CP_COMMIT() asm volatile("cp.async.commit_group;" ::: "memory")
#define CP_WAIT1()  asm volatile("cp.async.wait_group 1;" ::: "memory")
#define CP_WAIT0()  asm volatile("cp.async.wait_group 0;" ::: "memory")

// ---------------------------------------------------------------------------
// Elementwise tf32 rounding
// ---------------------------------------------------------------------------
__global__ void round_tf(const float* __restrict__ in, float* __restrict__ out) {
    size_t i = ((size_t)blockIdx.x * 256 + threadIdx.x) * 4;
    float4 v = *(const float4*)(in + i);
    *(float4*)(out + i) = make_float4(tf(v.x), tf(v.y), tf(v.z), tf(v.w));
}

// ---------------------------------------------------------------------------
// Weight transpose + round: out[n][k] = tf(in[k][n])
// ---------------------------------------------------------------------------
__global__ void transpose_k(const float* __restrict__ in, float* __restrict__ out, int K, int N) {
    __shared__ float t[32][33];
    int k0 = blockIdx.y * 32, n0 = blockIdx.x * 32;
    #pragma unroll
    for (int i = threadIdx.y; i < 32; i += 8)
        t[i][threadIdx.x] = in[(size_t)(k0 + i) * N + n0 + threadIdx.x];
    __syncthreads();
    #pragma unroll
    for (int i = threadIdx.y; i < 32; i += 8)
        out[(size_t)(n0 + i) * K + k0 + threadIdx.x] = tf(t[threadIdx.x][i]);
}

// ---------------------------------------------------------------------------
// V transpose per (b,h): g_v [n][d] -> g_vt [d][n]
// ---------------------------------------------------------------------------
__global__ void transpose_v() {
    __shared__ float t[32][33];
    int bh = blockIdx.z;
    const float* in = g_v + (size_t)bh * NTOT * DH;
    float* out = g_vt + (size_t)bh * DH * NTOT;
    int d0 = blockIdx.x * 32, n0 = blockIdx.y * 32;
    #pragma unroll
    for (int i = threadIdx.y; i < 32; i += 8)
        t[i][threadIdx.x] = in[(size_t)(n0 + i) * DH + d0 + threadIdx.x];
    __syncthreads();
    #pragma unroll
    for (int i = threadIdx.y; i < 32; i += 8)
        out[(size_t)(d0 + i) * NTOT + n0 + threadIdx.x] = t[threadIdx.x][i];
}

// ---------------------------------------------------------------------------
// tf32 mma.sync GEMM, cp.async 2-stage: C[M,N] = A[M,K] * Bt[N,K]^T
// CTA tile 128x256, BK=32. 8 warps as 2x4 grid of 64x64 warp tiles.
// ---------------------------------------------------------------------------
#define GSTR 36
#define GSA (128 * GSTR)                  // A stage floats (4608)
#define GSB (256 * GSTR)                  // B stage floats (9216)
#define GEMM_SMEM ((2 * GSA + 2 * GSB) * 4)   // 110592 B

__global__ __launch_bounds__(256) void mma_gemm(
    const float* __restrict__ A, const float* __restrict__ Bt,
    float* __restrict__ C, int M, int N, int K)
{
    extern __shared__ float sm[];
    uint32_t sbase = smem_u32(sm);
    int tid = threadIdx.x, lane = tid & 31, wid = tid >> 5;
    int wm = wid & 1, wn = wid >> 1;              // 2 x 4
    int row0 = blockIdx.y * 128, col0 = blockIdx.x * 256;
    int r = lane >> 2, c = lane & 3;
    int lr = tid >> 3, lc = (tid & 7) << 2;       // 32 rows/pass, 8 f4 cols
    int KT = K >> 5;

    auto issue = [&](int t, int s) {
        const float* ap = A + (size_t)(row0 + lr) * K + t * 32 + lc;
        const float* bp = Bt + (size_t)(col0 + lr) * K + t * 32 + lc;
        uint32_t da = sbase + (uint32_t)(s * GSA + lr * GSTR + lc) * 4u;
        uint32_t db = sbase + (uint32_t)(2 * GSA + s * GSB + lr * GSTR + lc) * 4u;
        #pragma unroll
        for (int i = 0; i < 4; i++)
            cpa16(da + (uint32_t)(i * 32 * GSTR) * 4u, ap + (size_t)(i * 32) * K);
        #pragma unroll
        for (int i = 0; i < 8; i++)
            cpa16(db + (uint32_t)(i * 32 * GSTR) * 4u, bp + (size_t)(i * 32) * K);
        CP_COMMIT();
    };

    float acc[4][8][4] = {};
    issue(0, 0);

    for (int t = 0; t < KT; t++) {
        int s = t & 1;
        if (t + 1 < KT) { issue(t + 1, s ^ 1); CP_WAIT1(); } else { CP_WAIT0(); }
        __syncthreads();
        const float* As = sm + s * GSA;
        const float* Bs = sm + 2 * GSA + s * GSB;

        #pragma unroll
        for (int ks = 0; ks < 4; ks++) {
            uint32_t af[4][4], bf[8][2];
            #pragma unroll
            for (int mi = 0; mi < 4; mi++) {
                const float* p = &As[(wm * 64 + mi * 16 + r) * GSTR + ks * 8 + c];
                af[mi][0] = __float_as_uint(p[0]);
                af[mi][1] = __float_as_uint(p[8 * GSTR]);
                af[mi][2] = __float_as_uint(p[4]);
                af[mi][3] = __float_as_uint(p[8 * GSTR + 4]);
            }
            #pragma unroll
            for (int ni = 0; ni < 8; ni++) {
                const float* p = &Bs[(wn * 64 + ni * 8 + r) * GSTR + ks * 8 + c];
                bf[ni][0] = __float_as_uint(p[0]);
                bf[ni][1] = __float_as_uint(p[4]);
            }
            #pragma unroll
            for (int mi = 0; mi < 4; mi++)
                #pragma unroll
                for (int ni = 0; ni < 8; ni++)
                    mma8(acc[mi][ni], af[mi], bf[ni]);
        }
        __syncthreads();
    }

    #pragma unroll
    for (int mi = 0; mi < 4; mi++) {
        int row = row0 + wm * 64 + mi * 16 + r;
        #pragma unroll
        for (int ni = 0; ni < 8; ni++) {
            int col = col0 + wn * 64 + ni * 8 + 2 * c;
            *(float2*)&C[(size_t)row * N + col] = make_float2(acc[mi][ni][0], acc[mi][ni][1]);
            *(float2*)&C[(size_t)(row + 8) * N + col] = make_float2(acc[mi][ni][2], acc[mi][ni][3]);
        }
    }
}

// ---------------------------------------------------------------------------
// QKV transform: RMSNorm q (D^-0.5 folded), k; scatter (tf32-rounded)
// ---------------------------------------------------------------------------
__global__ __launch_bounds__(256) void qkv_transform(
    const float* __restrict__ qg0, const float* __restrict__ kg0,
    const float* __restrict__ qg1, const float* __restrict__ kg1)
{
    int gw = (blockIdx.x * blockDim.x + threadIdx.x) >> 5;
    int lane = threadIdx.x & 31;
    int h = gw & (H - 1);
    int bn = gw >> 4;
    int n = bn & (NTOT - 1);
    int b = bn >> 11;

    const float *src, *qg, *kg;
    size_t rowoff;
    if (n < N0) { src = g_qkv0; rowoff = (size_t)(b * N0 + n) * (3 * DI); qg = qg0; kg = kg0; }
    else        { src = g_qkv1; rowoff = (size_t)(b * N1 + (n - N0)) * (3 * DI); qg = qg1; kg = kg1; }

    const float* qp = src + rowoff + h * DH;
    const float* kp = qp + DI;
    const float* vp = qp + 2 * DI;
    float q0 = qp[lane], q1 = qp[lane + 32];
    float k0 = kp[lane], k1 = kp[lane + 32];
    float v0 = vp[lane], v1 = vp[lane + 32];

    float qs = q0 * q0 + q1 * q1, ks = k0 * k0 + k1 * k1;
    #pragma unroll
    for (int off = 16; off; off >>= 1) {
        qs += __shfl_xor_sync(0xFFFFFFFFu, qs, off);
        ks += __shfl_xor_sync(0xFFFFFFFFu, ks, off);
    }
    float qinv = 1.0f / fmaxf(sqrtf(qs), 1e-12f);   // 8 * 0.125 = 1
    float kinv = 8.0f / fmaxf(sqrtf(ks), 1e-12f);

    size_t dst = ((size_t)(b * H + h) * NTOT + n) * DH;
    g_q[dst + lane]      = tf(q0 * qinv * qg[h * DH + lane]);
    g_q[dst + lane + 32] = tf(q1 * qinv * qg[h * DH + lane + 32]);
    g_k[dst + lane]      = tf(k0 * kinv * kg[h * DH + lane]);
    g_k[dst + lane + 32] = tf(k1 * kinv * kg[h * DH + lane + 32]);
    g_v[dst + lane]      = tf(v0);
    g_v[dst + lane + 32] = tf(v1);
}

// ---------------------------------------------------------------------------
// Attention (mma.sync flash, cp.async 2-stage K/VT). CTA = 256 q x one (b,h).
// 256 thr, 8 warps x 32q each (warp tile 32q x 64k, mi=2), 32 key chunks of 64.
// smem floats: Q @0 (256x68), K 2x(64x68) @17408, VT 2x(64x68) @26112,
//              P @34816 (256x68). Total 52224 f = 208896 B.
// ---------------------------------------------------------------------------
#define ASTR 68
#define AQ  0
#define AK(s)  (17408 + (s) * 4352)
#define AV(s)  (26112 + (s) * 4352)
#define AP  34816
#define ATT_SMEM (52224 * 4)

__global__ __launch_bounds__(256) void attention_mma()
{
    extern __shared__ float sm[];
    uint32_t sbase = smem_u32(sm);
    int tid = threadIdx.x, lane = tid & 31, wid = tid >> 5;
    int wq = wid * 32;
    int bh = blockIdx.y;
    int q0 = blockIdx.x * 256;
    size_t base = (size_t)bh * NTOT * DH;
    const float* Vt = g_vt + (size_t)bh * DH * NTOT;
    int r = lane >> 2, c = lane & 3;

    int kvr = tid >> 2, kvc4 = tid & 3;   // K/VT: 64 rows x 4 f4-groups/thr

    auto issueKV = [&](int kc, int s) {
        const float* kp = g_k + base + (size_t)(kc * 64 + kvr) * DH;
        const float* vp = Vt + (size_t)kvr * NTOT + kc * 64;
        uint32_t dk = sbase + (uint32_t)(AK(s) + kvr * ASTR) * 4u;
        uint32_t dv = sbase + (uint32_t)(AV(s) + kvr * ASTR) * 4u;
        #pragma unroll
        for (int i = 0; i < 4; i++) {
            int f = (kvc4 + 4 * i) * 4;
            cpa16(dk + (uint32_t)f * 4u, kp + f);
            cpa16(dv + (uint32_t)f * 4u, vp + f);
        }
    };

    // group 0: Q tile (256 rows, one row per thread) + chunk 0
    {
        const float* qp = g_q + base + (size_t)(q0 + tid) * DH;
        uint32_t dq = sbase + (uint32_t)(AQ + tid * ASTR) * 4u;
        #pragma unroll
        for (int i = 0; i < 16; i++)
            cpa16(dq + (uint32_t)(i * 4) * 4u, qp + i * 4);
        issueKV(0, 0);
        CP_COMMIT();
    }

    const float C1 = 72.134752f, C2 = -24.0449173f, C3 = 9.6179669f; // 50*log2e*{1,-1/3,2/15}
    float oacc[2][8][4] = {};
    float rs[4] = {};   // rows wq + r + {0,8,16,24}

    for (int kc = 0; kc < 32; kc++) {
        int s = kc & 1;
        if (kc + 1 < 32) { issueKV(kc + 1, s ^ 1); CP_COMMIT(); CP_WAIT1(); }
        else             { CP_WAIT0(); }
        __syncthreads();

        // S = Q K^T  (warp: 32q x 64k)
        float sacc[2][8][4] = {};
        #pragma unroll
        for (int ks = 0; ks < 8; ks++) {
            uint32_t af[2][4];
            #pragma unroll
            for (int mi = 0; mi < 2; mi++) {
                const float* pa = &sm[AQ + (wq + mi * 16 + r) * ASTR + ks * 8 + c];
                af[mi][0] = __float_as_uint(pa[0]);
                af[mi][1] = __float_as_uint(pa[8 * ASTR]);
                af[mi][2] = __float_as_uint(pa[4]);
                af[mi][3] = __float_as_uint(pa[8 * ASTR + 4]);
            }
            #pragma unroll
            for (int ni = 0; ni < 8; ni++) {
                uint32_t bf[2];
                const float* pb = &sm[AK(s) + (ni * 8 + r) * ASTR + ks * 8 + c];
                bf[0] = __float_as_uint(pb[0]);
                bf[1] = __float_as_uint(pb[4]);
                #pragma unroll
                for (int mi = 0; mi < 2; mi++)
                    mma8(sacc[mi][ni], af[mi], bf);
            }
        }

        // softmax (softclamp poly + exp2) -> P smem (per-warp rows)
        #pragma unroll
        for (int mi = 0; mi < 2; mi++)
            #pragma unroll
            for (int ni = 0; ni < 8; ni++) {
                float p[4];
                #pragma unroll
                for (int j = 0; j < 4; j++) {
                    float x = sacc[mi][ni][j] * 0.02f;
                    float x2 = x * x;
                    float u = x * fmaf(x2, fmaf(x2, C3, C2), C1);
                    p[j] = ex2f(u);
                }
                rs[mi * 2]     += p[0] + p[1];
                rs[mi * 2 + 1] += p[2] + p[3];
                *(float2*)&sm[AP + (wq + mi * 16 + r) * ASTR + ni * 8 + 2 * c]     = make_float2(tf(p[0]), tf(p[1]));
                *(float2*)&sm[AP + (wq + mi * 16 + r + 8) * ASTR + ni * 8 + 2 * c] = make_float2(tf(p[2]), tf(p[3]));
            }
        __syncwarp();

        // O += P V  (warp: 32q x 64d)
        #pragma unroll
        for (int ks = 0; ks < 8; ks++) {
            uint32_t af[2][4];
            #pragma unroll
            for (int mi = 0; mi < 2; mi++) {
                const float* pa = &sm[AP + (wq + mi * 16 + r) * ASTR + ks * 8 + c];
                af[mi][0] = __float_as_uint(pa[0]);
                af[mi][1] = __float_as_uint(pa[8 * ASTR]);
                af[mi][2] = __float_as_uint(pa[4]);
                af[mi][3] = __float_as_uint(pa[8 * ASTR + 4]);
            }
            #pragma unroll
            for (int ni = 0; ni < 8; ni++) {
                uint32_t bf[2];
                const float* pb = &sm[AV(s) + (ni * 8 + r) * ASTR + ks * 8 + c];
                bf[0] = __float_as_uint(pb[0]);
                bf[1] = __float_as_uint(pb[4]);
                #pragma unroll
                for (int mi = 0; mi < 2; mi++)
                    mma8(oacc[mi][ni], af[mi], bf);
            }
        }
        __syncthreads();
    }

    #pragma unroll
    for (int i = 0; i < 4; i++) {
        rs[i] += __shfl_xor_sync(0xFFFFFFFFu, rs[i], 1);
        rs[i] += __shfl_xor_sync(0xFFFFFFFFu, rs[i], 2);
        rs[i] = 1.0f / rs[i];
    }

    int b = bh >> 4, h = bh & (H - 1);
    #pragma unroll
    for (int mi = 0; mi < 2; mi++) {
        int row = q0 + wq + mi * 16 + r;
        float* op  = g_o + (size_t)(b * NTOT + row) * DI + h * DH;
        float* op8 = op + (size_t)8 * DI;
        float i0 = rs[mi * 2], i1 = rs[mi * 2 + 1];
        #pragma unroll
        for (int ni = 0; ni < 8; ni++) {
            int col = ni * 8 + 2 * c;
            *(float2*)&op[col]  = make_float2(tf(oacc[mi][ni][0] * i0), tf(oacc[mi][ni][1] * i0));
            *(float2*)&op8[col] = make_float2(tf(oacc[mi][ni][2] * i1), tf(oacc[mi][ni][3] * i1));
        }
    }
}

// ---------------------------------------------------------------------------
extern "C" void kernel_launch(void* const* d_in, const int* in_sizes, int n_in,
                              void* d_out, int out_size)
{
    const float* x0    = (const float*)d_in[0];
    const float* x1    = (const float*)d_in[1];
    const float* Wqkv0 = (const float*)d_in[2];
    const float* Wqkv1 = (const float*)d_in[3];
    const float* qg0   = (const float*)d_in[4];
    const float* kg0   = (const float*)d_in[5];
    const float* qg1   = (const float*)d_in[6];
    const float* kg1   = (const float*)d_in[7];
    const float* Wout0 = (const float*)d_in[8];
    const float* Wout1 = (const float*)d_in[9];
    float* out = (float*)d_out;

    float *qkv0, *qkv1, *o, *wt0, *wt1, *wtO0, *wtO1, *x0r, *x1r;
    cudaGetSymbolAddress((void**)&qkv0, g_qkv0);
    cudaGetSymbolAddress((void**)&qkv1, g_qkv1);
    cudaGetSymbolAddress((void**)&o,    g_o);
    cudaGetSymbolAddress((void**)&wt0,  g_wt0);
    cudaGetSymbolAddress((void**)&wt1,  g_wt1);
    cudaGetSymbolAddress((void**)&wtO0, g_wtO0);
    cudaGetSymbolAddress((void**)&wtO1, g_wtO1);
    cudaGetSymbolAddress((void**)&x0r,  g_x0r);
    cudaGetSymbolAddress((void**)&x1r,  g_x1r);

    cudaFuncSetAttribute(mma_gemm, cudaFuncAttributeMaxDynamicSharedMemorySize, GEMM_SMEM);
    cudaFuncSetAttribute(attention_mma, cudaFuncAttributeMaxDynamicSharedMemorySize, ATT_SMEM);

    dim3 t8(32, 8);
    round_tf<<<(B * N0 * D0) / 1024, 256>>>(x0, x0r);
    round_tf<<<(B * N1 * D1) / 1024, 256>>>(x1, x1r);
    transpose_k<<<dim3(3 * DI / 32, D0 / 32), t8>>>(Wqkv0, wt0, D0, 3 * DI);
    transpose_k<<<dim3(3 * DI / 32, D1 / 32), t8>>>(Wqkv1, wt1, D1, 3 * DI);
    transpose_k<<<dim3(D0 / 32, DI / 32), t8>>>(Wout0, wtO0, DI, D0);
    transpose_k<<<dim3(D1 / 32, DI / 32), t8>>>(Wout1, wtO1, DI, D1);

    mma_gemm<<<dim3(3 * DI / 256, B * N0 / 128), 256, GEMM_SMEM>>>(x0r, wt0, qkv0, B * N0, 3 * DI, D0);
    mma_gemm<<<dim3(3 * DI / 256, B * N1 / 128), 256, GEMM_SMEM>>>(x1r, wt1, qkv1, B * N1, 3 * DI, D1);

    qkv_transform<<<(B * NTOT * H) / 8, 256>>>(qg0, kg0, qg1, kg1);
    transpose_v<<<dim3(DH / 32, NTOT / 32, B * H), t8>>>();

    attention_mma<<<dim3(NTOT / 256, B * H), 256, ATT_SMEM>>>();

    float* out1 = out + (size_t)B * N0 * D0;
    for (int b = 0; b < B; b++) {
        mma_gemm<<<dim3(D0 / 256, N0 / 128), 256, GEMM_SMEM>>>(
            o + (size_t)b * NTOT * DI, wtO0, out + (size_t)b * N0 * D0, N0, D0, DI);
        mma_gemm<<<dim3(D1 / 256, N1 / 128), 256, GEMM_SMEM>>>(
            o + ((size_t)b * NTOT + N0) * DI, wtO1, out1 + (size_t)b * N1 * D1, N1, D1, DI);
    }
}